// round 10
// baseline (speedup 1.0000x reference)
#include <cuda_runtime.h>
#include <cstdint>

// Idx2PixelLayer: bilinear gather of N=1e6 points from a 2048x2048x8 fp32 image.
// c = ((coord - 1) mod (dim - 4)) + 1   (non-negative mod, JAX semantics)
// out = w00*g(0,0) + w10*g(1,0) + w01*g(0,1) + w11*g(1,1)
//   w00=d0*d1, w10=(1-d0)*d1, w01=d0*(1-d1), w11=(1-d0)*(1-d1)
// Reference's off-mask is always false (c <= 2045 < 2048), so dropped.
//
// R9: IN-BLOCK BINNING, ONE LAUNCH. Grid = NBINS x NCHUNK, bin-major, so the
// ~1200 concurrently-resident blocks all work on the same ~2.5 image bins
// (8 bins x 256 rows x 16MB = image split; live window ~40MB, L2-resident).
// Each block sweeps one contiguous 2048-point coord chunk (coalesced; coords
// are 8MB and stay L2-resident across the 8 sweeps), compacts its bin's
// points into smem via warp-aggregated ballot, then processes them with the
// proven 2-threads/point layout (lane pairs cover one 32B pixel sector per
// gather). Image DRAM reads collapse toward unique-block compulsory traffic.

static constexpr int H = 2048;
static constexpr int W = 2048;
static constexpr int C = 8;

static constexpr int NBINS    = 8;
static constexpr int BINSHIFT = 8;      // i0 >> 8 : 256 rows per bin (16MB)
static constexpr int CHUNK    = 2048;   // points per block sweep
static constexpr int THREADS  = 256;
static constexpr int CAP      = 512;    // smem slots (mean 256, sd ~15)

struct SPoint {
    int   p;      // point id
    int   base;   // float offset of g(0,0), channel half 0
    float w00, w10, w01, w11;
};

__global__ __launch_bounds__(THREADS)
void idx2pixel_binned(const float2* __restrict__ coords,
                      const float*  __restrict__ visible,
                      float* __restrict__ out,
                      int n, int nchunk)
{
    __shared__ int    s_cnt;
    __shared__ SPoint s_pts[CAP];

    const int bin   = blockIdx.x / nchunk;   // bin-major: resident blocks share bins
    const int chunk = blockIdx.x % nchunk;
    const int tid   = threadIdx.x;
    const int lane  = tid & 31;
    const int p0    = chunk * CHUNK;
    const int RS    = W * C;

    if (tid == 0) s_cnt = 0;
    __syncthreads();

    const float m0 = (float)(H - 4);   // 2044
    const float m1 = (float)(W - 4);

    // ---- sweep + filter + warp-aggregated compaction ----
    for (int r = 0; r < CHUNK; r += THREADS) {
        int p = p0 + r + tid;
        bool act = (p < n);
        float2 xy = act ? __ldg(coords + p) : make_float2(1.0f, 1.0f);

        float c0 = fmodf(xy.x - 1.0f, m0); if (c0 < 0.0f) c0 += m0; c0 += 1.0f;
        float c1 = fmodf(xy.y - 1.0f, m1); if (c1 < 0.0f) c1 += m1; c1 += 1.0f;
        float f0 = floorf(c0);
        float f1 = floorf(c1);
        float d0 = c0 - f0;
        float d1 = c1 - f1;
        int   i0 = (int)f0;
        int   i1 = (int)f1;

        bool match = act && ((i0 >> BINSHIFT) == bin);

        unsigned m = __ballot_sync(0xffffffffu, match);
        int cnt   = __popc(m);
        int alloc = 0;
        if (cnt) {
            int leader = __ffs(m) - 1;
            if (lane == leader) alloc = atomicAdd(&s_cnt, cnt);
            alloc = __shfl_sync(0xffffffffu, alloc, leader);
        }

        if (match) {
            int slot = alloc + __popc(m & ((1u << lane) - 1u));
            if (slot < CAP) {
                SPoint sp;
                sp.p    = p;
                sp.base = (i0 * W + i1) * C;
                sp.w00  = d0 * d1;
                sp.w10  = (1.0f - d0) * d1;
                sp.w01  = d0 * (1.0f - d1);
                sp.w11  = (1.0f - d0) * (1.0f - d1);
                s_pts[slot] = sp;
            } else {
                // Statistically unreachable overflow guard: process inline.
                float w00 = d0 * d1, w10 = (1.0f - d0) * d1;
                float w01 = d0 * (1.0f - d1), w11 = (1.0f - d0) * (1.0f - d1);
                int base = (i0 * W + i1) * C;
                #pragma unroll
                for (int k = 0; k < 2; k++) {
                    const float4* q00 = reinterpret_cast<const float4*>(visible + base + 4*k);
                    const float4* q01 = reinterpret_cast<const float4*>(visible + base + 4*k + C);
                    const float4* q10 = reinterpret_cast<const float4*>(visible + base + 4*k + RS);
                    const float4* q11 = reinterpret_cast<const float4*>(visible + base + 4*k + RS + C);
                    float4 a00 = __ldg(q00), a01 = __ldg(q01), a10 = __ldg(q10), a11 = __ldg(q11);
                    float4 o;
                    o.x = w00*a00.x + w10*a10.x + w01*a01.x + w11*a11.x;
                    o.y = w00*a00.y + w10*a10.y + w01*a01.y + w11*a11.y;
                    o.z = w00*a00.z + w10*a10.z + w01*a01.z + w11*a11.z;
                    o.w = w00*a00.w + w10*a10.w + w01*a01.w + w11*a11.w;
                    __stcs(reinterpret_cast<float4*>(out + p * C + 4*k), o);
                }
            }
        }
    }
    __syncthreads();

    // ---- process compacted points: 2 threads per point ----
    int cnt = min(s_cnt, CAP);
    int k = tid & 1;                       // channel half: floats [4k, 4k+4)
    for (int i = tid >> 1; i < cnt; i += THREADS / 2) {
        SPoint sp = s_pts[i];
        int base = sp.base + 4 * k;

        const float4* q00 = reinterpret_cast<const float4*>(visible + base);
        const float4* q01 = reinterpret_cast<const float4*>(visible + base + C);
        const float4* q10 = reinterpret_cast<const float4*>(visible + base + RS);
        const float4* q11 = reinterpret_cast<const float4*>(visible + base + RS + C);

        float4 a00 = __ldg(q00);
        float4 a01 = __ldg(q01);
        float4 a10 = __ldg(q10);
        float4 a11 = __ldg(q11);

        float4 o;
        o.x = sp.w00*a00.x + sp.w10*a10.x + sp.w01*a01.x + sp.w11*a11.x;
        o.y = sp.w00*a00.y + sp.w10*a10.y + sp.w01*a01.y + sp.w11*a11.y;
        o.z = sp.w00*a00.z + sp.w10*a10.z + sp.w01*a01.z + sp.w11*a11.z;
        o.w = sp.w00*a00.w + sp.w10*a10.w + sp.w01*a01.w + sp.w11*a11.w;

        __stcs(reinterpret_cast<float4*>(out + sp.p * C + 4 * k), o);
    }
}

extern "C" void kernel_launch(void* const* d_in, const int* in_sizes, int n_in,
                              void* d_out, int out_size)
{
    const float2* coords  = (const float2*)d_in[0];  // [N, 2] fp32
    const float*  visible = (const float*)d_in[1];   // [H, W, C] fp32
    float* out = (float*)d_out;                      // [N, C] fp32

    int n = in_sizes[0] / 2;   // number of points
    (void)n_in; (void)out_size;

    int nchunk = (n + CHUNK - 1) / CHUNK;            // 489 for n=1e6
    int blocks = NBINS * nchunk;                     // bin-major grid
    idx2pixel_binned<<<blocks, THREADS>>>(coords, visible, out, n, nchunk);
}

// round 11
// speedup vs baseline: 1.0856x; 1.0856x over previous
#include <cuda_runtime.h>
#include <cstdint>

// Idx2PixelLayer: bilinear gather of N=1e6 points from a 2048x2048x8 fp32 image.
// c = ((coord - 1) mod (dim - 4)) + 1   (non-negative mod, JAX semantics)
// out = w00*g(0,0) + w10*g(1,0) + w01*g(0,1) + w11*g(1,1)
//   w00=d0*d1, w10=(1-d0)*d1, w01=d0*(1-d1), w11=(1-d0)*(1-d1)
// Reference's off-mask is always false (c <= 2045 < 2048), so dropped.
//
// R10: in-block binning with a CHEAP bin filter. R9 proved bin-major
// scheduling cuts DRAM traffic 198->147MB, but doing the full fmodf point
// math 8x per point made it issue-bound. The bin only needs a consistent
// partition correlated with i0, so use bin = clamp((int)x,0,2047)>>8 (~6
// instructions). It equals i0>>8 for all x>=1; the x<1 wrap cases land in
// bin 0 instead of 7 -- still processed exactly once, correctness unaffected.
// Full fmod math runs once per point in the processing phase; matched coords
// are staged in smem. Bin-major grid => ~1200 resident blocks share ~2.5
// bins (~40MB image window, L2-resident) => duplicate pixel hits dedup in L2.
// Processing keeps the proven 2-threads/point layout (lane pair = one 32B
// pixel sector per gather); output sectors stay fully written (no RMW).

static constexpr int H = 2048;
static constexpr int W = 2048;
static constexpr int C = 8;

static constexpr int NBINS    = 8;
static constexpr int BINSHIFT = 8;      // 256 rows per bin (16MB of image)
static constexpr int CHUNK    = 2048;   // points per block sweep
static constexpr int THREADS  = 256;
static constexpr int CAP      = 512;    // smem slots (mean 256, sd ~15)

__global__ __launch_bounds__(THREADS)
void idx2pixel_binned(const float2* __restrict__ coords,
                      const float*  __restrict__ visible,
                      float* __restrict__ out,
                      int n, int nchunk)
{
    __shared__ int    s_cnt;
    __shared__ int    s_id[CAP];
    __shared__ float2 s_xy[CAP];

    const int bin   = blockIdx.x / nchunk;   // bin-major: resident blocks share bins
    const int chunk = blockIdx.x % nchunk;
    const int tid   = threadIdx.x;
    const int lane  = tid & 31;
    const int p0    = chunk * CHUNK;
    const int RS    = W * C;

    if (tid == 0) s_cnt = 0;
    __syncthreads();

    // ---- sweep + CHEAP filter + warp-aggregated compaction ----
    for (int r = 0; r < CHUNK; r += THREADS) {
        int p = p0 + r + tid;
        bool act = (p < n);
        float2 xy = act ? __ldg(coords + p) : make_float2(0.0f, 0.0f);

        // Cheap consistent bin: equals i0>>8 for x>=1; wrap cases -> bin 0.
        int bx = min(max((int)xy.x, 0), H - 1);
        bool match = act && ((bx >> BINSHIFT) == bin);

        unsigned m = __ballot_sync(0xffffffffu, match);
        int cnt   = __popc(m);
        int alloc = 0;
        if (cnt) {
            int leader = __ffs(m) - 1;
            if (lane == leader) alloc = atomicAdd(&s_cnt, cnt);
            alloc = __shfl_sync(0xffffffffu, alloc, leader);
        }

        if (match) {
            int slot = alloc + __popc(m & ((1u << lane) - 1u));
            if (slot < CAP) {
                s_id[slot] = p;
                s_xy[slot] = xy;
            } else {
                // Statistically unreachable overflow guard: process inline.
                const float m0 = (float)(H - 4), m1 = (float)(W - 4);
                float c0 = fmodf(xy.x - 1.0f, m0); if (c0 < 0.0f) c0 += m0; c0 += 1.0f;
                float c1 = fmodf(xy.y - 1.0f, m1); if (c1 < 0.0f) c1 += m1; c1 += 1.0f;
                float f0 = floorf(c0), f1 = floorf(c1);
                float d0 = c0 - f0,  d1 = c1 - f1;
                int base = ((int)f0 * W + (int)f1) * C;
                float w00 = d0*d1, w10 = (1.0f-d0)*d1, w01 = d0*(1.0f-d1), w11 = (1.0f-d0)*(1.0f-d1);
                #pragma unroll
                for (int k = 0; k < 2; k++) {
                    const float4* q00 = reinterpret_cast<const float4*>(visible + base + 4*k);
                    const float4* q01 = reinterpret_cast<const float4*>(visible + base + 4*k + C);
                    const float4* q10 = reinterpret_cast<const float4*>(visible + base + 4*k + RS);
                    const float4* q11 = reinterpret_cast<const float4*>(visible + base + 4*k + RS + C);
                    float4 a00 = __ldg(q00), a01 = __ldg(q01), a10 = __ldg(q10), a11 = __ldg(q11);
                    float4 o;
                    o.x = w00*a00.x + w10*a10.x + w01*a01.x + w11*a11.x;
                    o.y = w00*a00.y + w10*a10.y + w01*a01.y + w11*a11.y;
                    o.z = w00*a00.z + w10*a10.z + w01*a01.z + w11*a11.z;
                    o.w = w00*a00.w + w10*a10.w + w01*a01.w + w11*a11.w;
                    __stcs(reinterpret_cast<float4*>(out + p * C + 4*k), o);
                }
            }
        }
    }
    __syncthreads();

    // ---- process compacted points: 2 threads per point, full math once ----
    int cnt = min(s_cnt, CAP);
    int k = tid & 1;                       // channel half: floats [4k, 4k+4)
    const float m0 = (float)(H - 4), m1 = (float)(W - 4);

    for (int i = tid >> 1; i < cnt; i += THREADS / 2) {
        int    p  = s_id[i];
        float2 xy = s_xy[i];

        float c0 = fmodf(xy.x - 1.0f, m0); if (c0 < 0.0f) c0 += m0; c0 += 1.0f;
        float c1 = fmodf(xy.y - 1.0f, m1); if (c1 < 0.0f) c1 += m1; c1 += 1.0f;
        float f0 = floorf(c0), f1 = floorf(c1);
        float d0 = c0 - f0,  d1 = c1 - f1;
        int base = ((int)f0 * W + (int)f1) * C + 4 * k;

        const float4* q00 = reinterpret_cast<const float4*>(visible + base);
        const float4* q01 = reinterpret_cast<const float4*>(visible + base + C);
        const float4* q10 = reinterpret_cast<const float4*>(visible + base + RS);
        const float4* q11 = reinterpret_cast<const float4*>(visible + base + RS + C);

        float4 a00 = __ldg(q00);
        float4 a01 = __ldg(q01);
        float4 a10 = __ldg(q10);
        float4 a11 = __ldg(q11);

        float w00 = d0 * d1;
        float w10 = (1.0f - d0) * d1;
        float w01 = d0 * (1.0f - d1);
        float w11 = (1.0f - d0) * (1.0f - d1);

        float4 o;
        o.x = w00*a00.x + w10*a10.x + w01*a01.x + w11*a11.x;
        o.y = w00*a00.y + w10*a10.y + w01*a01.y + w11*a11.y;
        o.z = w00*a00.z + w10*a10.z + w01*a01.z + w11*a11.z;
        o.w = w00*a00.w + w10*a10.w + w01*a01.w + w11*a11.w;

        __stcs(reinterpret_cast<float4*>(out + p * C + 4 * k), o);
    }
}

extern "C" void kernel_launch(void* const* d_in, const int* in_sizes, int n_in,
                              void* d_out, int out_size)
{
    const float2* coords  = (const float2*)d_in[0];  // [N, 2] fp32
    const float*  visible = (const float*)d_in[1];   // [H, W, C] fp32
    float* out = (float*)d_out;                      // [N, C] fp32

    int n = in_sizes[0] / 2;   // number of points
    (void)n_in; (void)out_size;

    int nchunk = (n + CHUNK - 1) / CHUNK;            // 489 for n=1e6
    int blocks = NBINS * nchunk;                     // bin-major grid
    idx2pixel_binned<<<blocks, THREADS>>>(coords, visible, out, n, nchunk);
}

// round 12
// speedup vs baseline: 1.3311x; 1.2262x over previous
#include <cuda_runtime.h>
#include <cstdint>

// Idx2PixelLayer: bilinear gather of N=1e6 points from a 2048x2048x8 fp32 image.
// c = ((coord - 1) mod (dim - 4)) + 1   (non-negative mod, JAX semantics)
// out = w00*g(0,0) + w10*g(1,0) + w01*g(0,1) + w11*g(1,1)
//   w00=d0*d1, w10=(1-d0)*d1, w01=d0*(1-d1), w11=(1-d0)*(1-d1)
// Reference's off-mask is always false (c <= 2045 < 2048), so dropped.
//
// R11: binning with NBINS=2 (the sweep cost is proportional to NBINS; R10's
// NBINS=8 was issue-bound on 8x-redundant filtering). Two 64MB half-image
// bins; CHUNK=512 so each bin spans 1954 blocks and the ~1184-block resident
// wave covers only ~0.6 of a bin => ~40MB concurrent image window, which is
// L2-resident together with streaming coords/output. Duplicate pixel hits
// dedup in L2 -> image DRAM ~unique blocks only. Cheap consistent bin filter
// (clamp((int)x)>>10; x<1 wrap points land in bin 0, processed exactly once).
// Process phase: proven 2-threads/point layout (lane pair covers one 32B
// pixel sector per gather; output sectors fully written).

static constexpr int H = 2048;
static constexpr int W = 2048;
static constexpr int C = 8;

static constexpr int NBINS    = 2;
static constexpr int BINSHIFT = 10;     // 1024 rows per bin (64MB of image)
static constexpr int CHUNK    = 512;    // points per block sweep
static constexpr int THREADS  = 256;
static constexpr int CAP      = 384;    // smem slots (mean 256, sd ~11)

__global__ __launch_bounds__(THREADS)
void idx2pixel_binned(const float2* __restrict__ coords,
                      const float*  __restrict__ visible,
                      float* __restrict__ out,
                      int n, int nchunk)
{
    __shared__ int    s_cnt;
    __shared__ int    s_id[CAP];
    __shared__ float2 s_xy[CAP];

    const int bin   = blockIdx.x / nchunk;   // bin-major: resident wave stays in one bin
    const int chunk = blockIdx.x % nchunk;
    const int tid   = threadIdx.x;
    const int lane  = tid & 31;
    const int p0    = chunk * CHUNK;
    const int RS    = W * C;

    if (tid == 0) s_cnt = 0;
    __syncthreads();

    // ---- sweep + cheap filter + warp-aggregated compaction ----
    #pragma unroll
    for (int r = 0; r < CHUNK; r += THREADS) {
        int p = p0 + r + tid;
        bool act = (p < n);
        float2 xy = act ? __ldg(coords + p) : make_float2(0.0f, 0.0f);

        // Cheap consistent bin: equals i0>>10 for x>=1; wrap cases -> bin 0.
        int bx = min(max((int)xy.x, 0), H - 1);
        bool match = act && ((bx >> BINSHIFT) == bin);

        unsigned m = __ballot_sync(0xffffffffu, match);
        int cnt   = __popc(m);
        int alloc = 0;
        if (cnt) {
            int leader = __ffs(m) - 1;
            if (lane == leader) alloc = atomicAdd(&s_cnt, cnt);
            alloc = __shfl_sync(0xffffffffu, alloc, leader);
        }

        if (match) {
            int slot = alloc + __popc(m & ((1u << lane) - 1u));
            if (slot < CAP) {
                s_id[slot] = p;
                s_xy[slot] = xy;
            } else {
                // Statistically unreachable overflow guard: process inline.
                const float m0 = (float)(H - 4), m1 = (float)(W - 4);
                float c0 = fmodf(xy.x - 1.0f, m0); if (c0 < 0.0f) c0 += m0; c0 += 1.0f;
                float c1 = fmodf(xy.y - 1.0f, m1); if (c1 < 0.0f) c1 += m1; c1 += 1.0f;
                float f0 = floorf(c0), f1 = floorf(c1);
                float d0 = c0 - f0,  d1 = c1 - f1;
                int base = ((int)f0 * W + (int)f1) * C;
                float w00 = d0*d1, w10 = (1.0f-d0)*d1, w01 = d0*(1.0f-d1), w11 = (1.0f-d0)*(1.0f-d1);
                #pragma unroll
                for (int k = 0; k < 2; k++) {
                    const float4* q00 = reinterpret_cast<const float4*>(visible + base + 4*k);
                    const float4* q01 = reinterpret_cast<const float4*>(visible + base + 4*k + C);
                    const float4* q10 = reinterpret_cast<const float4*>(visible + base + 4*k + RS);
                    const float4* q11 = reinterpret_cast<const float4*>(visible + base + 4*k + RS + C);
                    float4 a00 = __ldg(q00), a01 = __ldg(q01), a10 = __ldg(q10), a11 = __ldg(q11);
                    float4 o;
                    o.x = w00*a00.x + w10*a10.x + w01*a01.x + w11*a11.x;
                    o.y = w00*a00.y + w10*a10.y + w01*a01.y + w11*a11.y;
                    o.z = w00*a00.z + w10*a10.z + w01*a01.z + w11*a11.z;
                    o.w = w00*a00.w + w10*a10.w + w01*a01.w + w11*a11.w;
                    __stcs(reinterpret_cast<float4*>(out + p * C + 4*k), o);
                }
            }
        }
    }
    __syncthreads();

    // ---- process compacted points: 2 threads per point, full math once ----
    int cnt = min(s_cnt, CAP);
    int k = tid & 1;                       // channel half: floats [4k, 4k+4)
    const float m0 = (float)(H - 4), m1 = (float)(W - 4);

    for (int i = tid >> 1; i < cnt; i += THREADS / 2) {
        int    p  = s_id[i];
        float2 xy = s_xy[i];

        float c0 = fmodf(xy.x - 1.0f, m0); if (c0 < 0.0f) c0 += m0; c0 += 1.0f;
        float c1 = fmodf(xy.y - 1.0f, m1); if (c1 < 0.0f) c1 += m1; c1 += 1.0f;
        float f0 = floorf(c0), f1 = floorf(c1);
        float d0 = c0 - f0,  d1 = c1 - f1;
        int base = ((int)f0 * W + (int)f1) * C + 4 * k;

        const float4* q00 = reinterpret_cast<const float4*>(visible + base);
        const float4* q01 = reinterpret_cast<const float4*>(visible + base + C);
        const float4* q10 = reinterpret_cast<const float4*>(visible + base + RS);
        const float4* q11 = reinterpret_cast<const float4*>(visible + base + RS + C);

        float4 a00 = __ldg(q00);
        float4 a01 = __ldg(q01);
        float4 a10 = __ldg(q10);
        float4 a11 = __ldg(q11);

        float w00 = d0 * d1;
        float w10 = (1.0f - d0) * d1;
        float w01 = d0 * (1.0f - d1);
        float w11 = (1.0f - d0) * (1.0f - d1);

        float4 o;
        o.x = w00*a00.x + w10*a10.x + w01*a01.x + w11*a11.x;
        o.y = w00*a00.y + w10*a10.y + w01*a01.y + w11*a11.y;
        o.z = w00*a00.z + w10*a10.z + w01*a01.z + w11*a11.z;
        o.w = w00*a00.w + w10*a10.w + w01*a01.w + w11*a11.w;

        __stcs(reinterpret_cast<float4*>(out + p * C + 4 * k), o);
    }
}

extern "C" void kernel_launch(void* const* d_in, const int* in_sizes, int n_in,
                              void* d_out, int out_size)
{
    const float2* coords  = (const float2*)d_in[0];  // [N, 2] fp32
    const float*  visible = (const float*)d_in[1];   // [H, W, C] fp32
    float* out = (float*)d_out;                      // [N, C] fp32

    int n = in_sizes[0] / 2;   // number of points
    (void)n_in; (void)out_size;

    int nchunk = (n + CHUNK - 1) / CHUNK;            // 1954 for n=1e6
    int blocks = NBINS * nchunk;                     // bin-major grid
    idx2pixel_binned<<<blocks, THREADS>>>(coords, visible, out, n, nchunk);
}